// round 10
// baseline (speedup 1.0000x reference)
#include <cuda_runtime.h>
#include <math.h>

#define S_LEN 1024
#define B_SZ  128
#define D_IN  64
#define H_SZ  512
#define NCTA  128
#define CHUNK 64

typedef unsigned long long ull;

// ------------------------- device scratch (allocation-free rule) -------------
__device__ float g_xT[S_LEN * D_IN * B_SZ];                 // [S][D][B]   32 MB
__device__ float g_h1[(size_t)S_LEN * H_SZ * B_SZ];         // [S][H][B]  256 MB
__device__ float g_h2[(size_t)S_LEN * H_SZ * B_SZ];         // [S][H][B]  256 MB
__device__ float g_hbuf[2][H_SZ * B_SZ];                    // double-buffered h
__device__ float g_e[B_SZ * S_LEN];                         // energies [B][S]
__device__ float g_att[B_SZ * S_LEN];                       // entmax weights
__device__ float g_pc[64 * 128 * 128];                      // partial contexts
__device__ float g_ctx[H_SZ * B_SZ];                        // context [H][B]
__device__ unsigned g_bar_count;
__device__ unsigned g_bar_gen;

// ------------------------- f32x2 helpers -------------------------------------
__device__ __forceinline__ ull dup2(float v) {
    ull r; asm("mov.b64 %0, {%1, %1};" : "=l"(r) : "f"(v)); return r;
}
__device__ __forceinline__ ull pk2(float lo, float hi) {
    ull r; asm("mov.b64 %0, {%1, %2};" : "=l"(r) : "f"(lo), "f"(hi)); return r;
}
__device__ __forceinline__ void unpk(ull v, float& lo, float& hi) {
    asm("mov.b64 {%0, %1}, %2;" : "=f"(lo), "=f"(hi) : "l"(v));
}
__device__ __forceinline__ ull fma2(ull a, ull b, ull c) {
    ull d; asm("fma.rn.f32x2 %0, %1, %2, %3;" : "=l"(d) : "l"(a), "l"(b), "l"(c));
    return d;
}
__device__ __forceinline__ float sigf(float v) { return 1.0f / (1.0f + expf(-v)); }

// ------------------------- cp.async helpers ----------------------------------
__device__ __forceinline__ void cpa16(float* smem_dst, const float* gmem_src) {
    unsigned s = (unsigned)__cvta_generic_to_shared(smem_dst);
    asm volatile("cp.async.cg.shared.global [%0], [%1], 16;" :: "r"(s), "l"(gmem_src));
}
#define CP_COMMIT() asm volatile("cp.async.commit_group;" ::: "memory")
#define CP_WAIT1()  asm volatile("cp.async.wait_group 1;" ::: "memory")
#define CP_WAIT0()  asm volatile("cp.async.wait_group 0;" ::: "memory")

// ------------------------- grid barrier (proven in R5/R8) --------------------
__device__ __forceinline__ unsigned gen_read() {
    unsigned v;
    asm volatile("ld.acquire.gpu.u32 %0, [%1];" : "=r"(v) : "l"(&g_bar_gen) : "memory");
    return v;
}
__device__ __forceinline__ void grid_barrier() {
    __syncthreads();
    if (threadIdx.x == 0) {
        unsigned target = gen_read() + 1u;          // read BEFORE arriving
        __threadfence();
        unsigned old = atomicAdd(&g_bar_count, 1u);
        if (old == NCTA - 1u) {
            atomicExch(&g_bar_count, 0u);
            __threadfence();
            atomicExch(&g_bar_gen, target);         // publish release
        } else {
            while ((int)(gen_read() - target) < 0) { __nanosleep(32); }
        }
        __threadfence();
    }
    __syncthreads();
}

// ------------------------- transpose x[B][S][D] -> xT[S][D][B] ---------------
__global__ void transpose_kernel(const float* __restrict__ x) {
    int idx = blockIdx.x * 256 + threadIdx.x;
    if (idx < S_LEN * D_IN * B_SZ) {
        int b = idx & (B_SZ - 1);
        int sd = idx >> 7;
        int d = sd & (D_IN - 1);
        int s = sd >> 6;
        g_xT[idx] = x[((size_t)b * S_LEN + s) * D_IN + d];
    }
}

// ------------------------- persistent LSTM layer -----------------------------
// CTA = 8 h-columns x 64 batches -> 32 gate rows. Weights in SMEM, layout
// [j][k][4 gates] (16B-aligned LDS.128 per k; (i,f)/(g,o) f32x2 halves).
// 512 threads: j = tid>>6 (h-col 0..7), lane64 = tid&63, 1 batch per thread.
// 4 warps per SMSP for latency hiding.
template <int KIN>
__global__ __launch_bounds__(512, 1) void lstm_kernel(
    const float* __restrict__ W_ih, const float* __restrict__ W_hh,
    const float* __restrict__ b_ih, const float* __restrict__ b_hh)
{
    constexpr int K = KIN + H_SZ;
    constexpr int NCH = K / CHUNK;
    extern __shared__ float wsm[];                 // [8 j][K][4 t]
    float* vbuf = wsm + 32 * K;                    // 2 x [CHUNK][64]
    __shared__ float bsm[32];                      // [j][4 t]

    const float* inSeq = (KIN == D_IN) ? g_xT : g_h1;
    float* outSeq      = (KIN == D_IN) ? g_h1 : g_h2;

    const int tid = threadIdx.x;
    const int cid = blockIdx.x;
    const int hg = cid >> 1;
    const int bg = cid & 1;
    const int hi0 = hg * 8;
    const int bbase = bg * 64;

    // weights: gate row r = t*H + hi0 + j, element k -> wsm[(j*K + k)*4 + t]
    for (int idx = tid; idx < 32 * K; idx += 512) {
        int row = idx / K;              // row = t*8 + j
        int k = idx - row * K;
        int t = row >> 3, j = row & 7;
        int r = t * H_SZ + hi0 + j;
        float w = (k < KIN) ? W_ih[(size_t)r * KIN + k]
                            : W_hh[(size_t)r * H_SZ + (k - KIN)];
        wsm[((size_t)j * K + k) * 4 + t] = w;
    }
    if (tid < 32) {
        int t = tid >> 3, j = tid & 7;
        int r = t * H_SZ + hi0 + j;
        bsm[j * 4 + t] = b_ih[r] + b_hh[r];
    }

    const int j = tid >> 6;             // 0..7
    const int lane64 = tid & 63;        // 0..63
    const int hi = hi0 + j;
    const int b0 = bbase + lane64;      // one batch per thread

    if (tid < 64) {                      // zero our h-slice rows (8 cols x 64 b)
        for (int jj = 0; jj < 8; ++jj)
            g_hbuf[0][(hi0 + jj) * B_SZ + bbase + tid] = 0.f;
    }

    // prefetch chunk 0 of step 0 (x-part: does not depend on h)
    {
        const float* src = inSeq + (size_t)0 * KIN * B_SZ + bbase;
#pragma unroll
        for (int u = 0; u < 2; ++u) {
            int op = u * 512 + tid;
            int row = op >> 4, seg = op & 15;
            cpa16(vbuf + row * 64 + seg * 4, src + (size_t)row * B_SZ + seg * 4);
        }
        CP_COMMIT();
    }
    __syncthreads();
    grid_barrier();

    // hoist biases into registers (scalar shared loads)
    float bi_i = bsm[j * 4 + 0];
    float bi_f = bsm[j * 4 + 1];
    float bi_g = bsm[j * 4 + 2];
    float bi_o = bsm[j * 4 + 3];
    const ull binit_if = pk2(bi_i, bi_f);
    const ull binit_go = pk2(bi_g, bi_o);

    float c0 = 0.f;
    const float* wj = wsm + (size_t)j * K * 4;
    int nb = 1;                                    // next buffer to fill

    for (int st = 0; st < S_LEN; ++st) {
        const float* hprev = g_hbuf[st & 1];
        float* hOut = g_hbuf[(st + 1) & 1];

        ull aif0 = binit_if, ago0 = binit_go;

        for (int ci = 0; ci < NCH; ++ci) {
            // issue next chunk
            bool issued = true;
            const float* src;
            if (ci + 1 < NCH) {
                int k0 = (ci + 1) * CHUNK;
                src = (k0 < KIN) ? inSeq + ((size_t)st * KIN + k0) * B_SZ + bbase
                                 : hprev + (size_t)(k0 - KIN) * B_SZ + bbase;
            } else if (st + 1 < S_LEN) {
                src = inSeq + (size_t)(st + 1) * KIN * B_SZ + bbase;  // x-part
            } else {
                issued = false; src = 0;
            }
            if (issued) {
                float* dst = vbuf + nb * (CHUNK * 64);
#pragma unroll
                for (int u = 0; u < 2; ++u) {
                    int op = u * 512 + tid;
                    int row = op >> 4, seg = op & 15;
                    cpa16(dst + row * 64 + seg * 4, src + (size_t)row * B_SZ + seg * 4);
                }
                CP_COMMIT();
                nb ^= 1;
            }
            if (issued) CP_WAIT1(); else CP_WAIT0();
            __syncthreads();

            // compute on the READY buffer (nb if just toggled, nb^1 otherwise)
            const float* cur = vbuf + (issued ? nb : (nb ^ 1)) * (CHUNK * 64);
            const ulonglong2* wk =
                (const ulonglong2*)(wj + (size_t)ci * CHUNK * 4);
#pragma unroll 8
            for (int kk = 0; kk < CHUNK; ++kk) {
                float v = cur[kk * 64 + lane64];
                ull v0 = dup2(v);
                ulonglong2 w2 = wk[kk];            // LDS.128: (wi,wf),(wg,wo)
                aif0 = fma2(w2.x, v0, aif0);
                ago0 = fma2(w2.y, v0, ago0);
            }
            __syncthreads();
        }

        float gi0, gf0, gg0, go0;
        unpk(aif0, gi0, gf0); unpk(ago0, gg0, go0);
        float cn0 = sigf(gf0) * c0 + sigf(gi0) * tanhf(gg0);
        float h0 = sigf(go0) * tanhf(cn0);
        c0 = cn0;
        hOut[hi * B_SZ + b0] = h0;
        outSeq[(size_t)st * H_SZ * B_SZ + (size_t)hi * B_SZ + b0] = h0;

        grid_barrier();
    }
}

// ------------------------- attention energies --------------------------------
__global__ __launch_bounds__(256) void energy_kernel(
    const float* __restrict__ Wa, const float* __restrict__ ba,
    const float* __restrict__ va, const float* __restrict__ bv)
{
    const int s = blockIdx.x;
    const int tid = threadIdx.x;
    const int tx = tid & 15, ty = tid >> 4;
    __shared__ float sWa[32][132];
    __shared__ float sIn[32][132];
    __shared__ float red[16][128];
    const float* h2s = g_h2 + (size_t)s * H_SZ * B_SZ;

    float epart[8];
#pragma unroll
    for (int q = 0; q < 8; ++q) epart[q] = 0.f;

    for (int gc = 0; gc < 4; ++gc) {
        const int g0 = gc * 128;
        float acc[8][8];
#pragma unroll
        for (int i = 0; i < 8; ++i)
#pragma unroll
            for (int q = 0; q < 8; ++q) acc[i][q] = 0.f;

        for (int kt = 0; kt < 16; ++kt) {
            const int k0 = kt * 32;
            __syncthreads();
            for (int idx = tid; idx < 4096; idx += 256) {
                int gg = idx >> 5, kk = idx & 31;
                sWa[kk][gg] = Wa[(size_t)(g0 + gg) * H_SZ + k0 + kk];
            }
            for (int idx = tid; idx < 4096; idx += 256) {
                int kk = idx >> 7, bb = idx & 127;
                sIn[kk][bb] = h2s[(size_t)(k0 + kk) * B_SZ + bb];
            }
            __syncthreads();
#pragma unroll 4
            for (int k = 0; k < 32; ++k) {
                float4 w0 = *(float4*)&sWa[k][tx * 8];
                float4 w1 = *(float4*)&sWa[k][tx * 8 + 4];
                float4 i0 = *(float4*)&sIn[k][ty * 8];
                float4 i1 = *(float4*)&sIn[k][ty * 8 + 4];
                float wv[8] = {w0.x, w0.y, w0.z, w0.w, w1.x, w1.y, w1.z, w1.w};
                float iv[8] = {i0.x, i0.y, i0.z, i0.w, i1.x, i1.y, i1.z, i1.w};
#pragma unroll
                for (int i = 0; i < 8; ++i)
#pragma unroll
                    for (int q = 0; q < 8; ++q) acc[i][q] += wv[i] * iv[q];
            }
        }
#pragma unroll
        for (int i = 0; i < 8; ++i) {
            int gidx = g0 + tx * 8 + i;
            float gv = va[gidx], bav = ba[gidx];
#pragma unroll
            for (int q = 0; q < 8; ++q) epart[q] += gv * tanhf(acc[i][q] + bav);
        }
    }
    __syncthreads();
#pragma unroll
    for (int q = 0; q < 8; ++q) red[tx][ty * 8 + q] = epart[q];
    __syncthreads();
    if (tid < 128) {
        float e = bv[0];
#pragma unroll
        for (int t = 0; t < 16; ++t) e += red[t][tid];
        g_e[(size_t)tid * S_LEN + s] = e;
    }
}

// ------------------------- entmax15 (faithful to reference) ------------------
__global__ __launch_bounds__(512) void entmax_kernel(float* __restrict__ dout)
{
    const int b = blockIdx.x;
    const int tid = threadIdx.x;
    __shared__ float xs[1024], xo[1024], sa[1024], sb[1024];
    __shared__ float rf[512];
    __shared__ int ri[512];
    const float* row = g_e + (size_t)b * S_LEN;

    xo[tid] = row[tid];
    xo[tid + 512] = row[tid + 512];
    __syncthreads();
    rf[tid] = fmaxf(xo[tid], xo[tid + 512]);
    __syncthreads();
    for (int off = 256; off > 0; off >>= 1) {
        if (tid < off) rf[tid] = fmaxf(rf[tid], rf[tid + off]);
        __syncthreads();
    }
    float mx = rf[0];
    __syncthreads();
    xo[tid] -= mx; xo[tid + 512] -= mx;
    xs[tid] = xo[tid]; xs[tid + 512] = xo[tid + 512];
    __syncthreads();

    for (int k = 2; k <= 1024; k <<= 1) {
        for (int jj = k >> 1; jj > 0; jj >>= 1) {
            for (int i = tid; i < 1024; i += 512) {
                int ixj = i ^ jj;
                if (ixj > i) {
                    bool up = ((i & k) == 0);
                    float a = xs[i], c2 = xs[ixj];
                    bool sw = up ? (a < c2) : (a > c2);
                    if (sw) { xs[i] = c2; xs[ixj] = a; }
                }
            }
            __syncthreads();
        }
    }

    sa[tid] = xs[tid]; sa[tid + 512] = xs[tid + 512];
    __syncthreads();
    float* pa = sa; float* pb = sb;
    for (int off = 1; off < 1024; off <<= 1) {
        for (int i = tid; i < 1024; i += 512)
            pb[i] = pa[i] + ((i >= off) ? pa[i - off] : 0.f);
        __syncthreads();
        float* t = pa; pa = pb; pb = t;
    }

    int cnt = 0;
    for (int i = tid; i < 1024; i += 512) {
        float sup = (float)(i + 1) * xs[i] - pa[i] + 0.5f;
        if (sup > 0.f) cnt++;
    }
    ri[tid] = cnt;
    __syncthreads();
    for (int off = 256; off > 0; off >>= 1) {
        if (tid < off) ri[tid] += ri[tid + off];
        __syncthreads();
    }
    int ssize = ri[0];
    if (ssize < 1) ssize = 1;
    if (ssize > 1023) ssize = 1023;
    float tau = ((float)(ssize + 1) * xs[ssize] - pa[ssize] + 0.5f) / (float)(ssize + 1);

    float d0 = xo[tid] - tau;
    float d1 = xo[tid + 512] - tau;
    float y0 = d0 > 0.f ? sqrtf(d0) : 0.f;
    float y1 = d1 > 0.f ? sqrtf(d1) : 0.f;
    __syncthreads();
    rf[tid] = y0 + y1;
    __syncthreads();
    for (int off = 256; off > 0; off >>= 1) {
        if (tid < off) rf[tid] += rf[tid + off];
        __syncthreads();
    }
    float inv = 1.f / rf[0];
    float w0 = y0 * inv, w1 = y1 * inv;
    g_att[(size_t)b * S_LEN + tid] = w0;
    g_att[(size_t)b * S_LEN + tid + 512] = w1;
    dout[128 + (size_t)b * S_LEN + tid] = w0;
    dout[128 + (size_t)b * S_LEN + tid + 512] = w1;
}

// ------------------------- context stage 1 -----------------------------------
__global__ __launch_bounds__(256) void ctx1_kernel()
{
    __shared__ float sAtt[64 * 128];
    const int bid = blockIdx.x;
    const int ch = bid >> 2, hq = bid & 3;
    const int s0 = ch * 64, h0 = hq * 128;
    const int tid = threadIdx.x;

    for (int idx = tid; idx < 64 * 128; idx += 256) {
        int sl = idx >> 7, bb = idx & 127;
        sAtt[idx] = g_att[(size_t)bb * S_LEN + s0 + sl];
    }
    __syncthreads();

    float racc[64];
#pragma unroll
    for (int u = 0; u < 64; ++u) racc[u] = 0.f;

    const int bcol = tid & 127;
    for (int sl = 0; sl < 64; ++sl) {
        const float* src = g_h2 + ((size_t)(s0 + sl) * H_SZ + h0) * B_SZ;
        float av = sAtt[sl * 128 + bcol];
#pragma unroll 8
        for (int u = 0; u < 64; ++u)
            racc[u] += av * __ldg(src + tid + u * 256);
    }
#pragma unroll
    for (int u = 0; u < 64; ++u)
        g_pc[(size_t)bid * 16384 + tid + u * 256] = racc[u];
}

// ------------------------- context stage 2 + FC ------------------------------
__global__ void ctx2_kernel()
{
    int e = blockIdx.x * 256 + threadIdx.x;
    if (e < H_SZ * B_SZ) {
        int h = e >> 7, bb = e & 127;
        int hq = h >> 7, hl = h & 127;
        float s = 0.f;
#pragma unroll
        for (int ch = 0; ch < 16; ++ch)
            s += g_pc[((size_t)(ch * 4 + hq) * 16384) + hl * 128 + bb];
        g_ctx[e] = s;
    }
}

__global__ void fc_kernel(const float* __restrict__ fcW,
                          const float* __restrict__ fcb,
                          float* __restrict__ out)
{
    int b = threadIdx.x;
    float a = fcb[0];
    for (int h = 0; h < H_SZ; ++h) a += fcW[h] * g_ctx[h * B_SZ + b];
    out[b] = a;
}

// ------------------------- launch --------------------------------------------
extern "C" void kernel_launch(void* const* d_in, const int* in_sizes, int n_in,
                              void* d_out, int out_size)
{
    (void)in_sizes; (void)n_in; (void)out_size;
    const float* x     = (const float*)d_in[0];
    const float* W_ih0 = (const float*)d_in[1];
    const float* W_hh0 = (const float*)d_in[2];
    const float* b_ih0 = (const float*)d_in[3];
    const float* b_hh0 = (const float*)d_in[4];
    const float* W_ih1 = (const float*)d_in[5];
    const float* W_hh1 = (const float*)d_in[6];
    const float* b_ih1 = (const float*)d_in[7];
    const float* b_hh1 = (const float*)d_in[8];
    const float* W_a   = (const float*)d_in[9];
    const float* b_a   = (const float*)d_in[10];
    const float* v_a   = (const float*)d_in[11];
    const float* b_v   = (const float*)d_in[12];
    const float* fc_W  = (const float*)d_in[13];
    const float* fc_b  = (const float*)d_in[14];
    float* out = (float*)d_out;

    const int smem0 = (32 * (D_IN + H_SZ) + 2 * CHUNK * 64) * 4;   // 106,496 B
    const int smem1 = (32 * (H_SZ + H_SZ) + 2 * CHUNK * 64) * 4;   // 163,840 B
    cudaFuncSetAttribute(lstm_kernel<D_IN>, cudaFuncAttributeMaxDynamicSharedMemorySize, smem0);
    cudaFuncSetAttribute(lstm_kernel<H_SZ>, cudaFuncAttributeMaxDynamicSharedMemorySize, smem1);

    transpose_kernel<<<(S_LEN * D_IN * B_SZ + 255) / 256, 256>>>(x);
    lstm_kernel<D_IN><<<NCTA, 512, smem0>>>(W_ih0, W_hh0, b_ih0, b_hh0);
    lstm_kernel<H_SZ><<<NCTA, 512, smem1>>>(W_ih1, W_hh1, b_ih1, b_hh1);
    energy_kernel<<<S_LEN, 256>>>(W_a, b_a, v_a, b_v);
    entmax_kernel<<<B_SZ, 512>>>(out);
    ctx1_kernel<<<64, 256>>>();
    ctx2_kernel<<<(H_SZ * B_SZ + 255) / 256, 256>>>();
    fc_kernel<<<1, 128>>>(fc_W, fc_b, out);
}

// round 11
// speedup vs baseline: 1.4463x; 1.4463x over previous
#include <cuda_runtime.h>
#include <math.h>

#define S_LEN 1024
#define B_SZ  128
#define D_IN  64
#define H_SZ  512
#define NCTA  128

typedef unsigned long long ull;

// ------------------------- device scratch (allocation-free rule) -------------
__device__ float g_xT[S_LEN * D_IN * B_SZ];                 // [S][D][B]   32 MB
__device__ float g_h1[(size_t)S_LEN * H_SZ * B_SZ];         // [S][H][B]  256 MB
__device__ float g_h2[(size_t)S_LEN * H_SZ * B_SZ];         // [S][H][B]  256 MB
__device__ float g_hbuf[2][H_SZ * B_SZ];                    // double-buffered h
__device__ float g_e[B_SZ * S_LEN];                         // energies [B][S]
__device__ float g_att[B_SZ * S_LEN];                       // entmax weights
__device__ float g_pc[64 * 128 * 128];                      // partial contexts
__device__ float g_ctx[H_SZ * B_SZ];                        // context [H][B]
__device__ unsigned g_bar_count;
__device__ unsigned g_bar_gen;

// ------------------------- f32x2 helpers -------------------------------------
__device__ __forceinline__ ull dup2(float v) {
    ull r; asm("mov.b64 %0, {%1, %1};" : "=l"(r) : "f"(v)); return r;
}
__device__ __forceinline__ ull pk2(float lo, float hi) {
    ull r; asm("mov.b64 %0, {%1, %2};" : "=l"(r) : "f"(lo), "f"(hi)); return r;
}
__device__ __forceinline__ void unpk(ull v, float& lo, float& hi) {
    asm("mov.b64 {%0, %1}, %2;" : "=f"(lo), "=f"(hi) : "l"(v));
}
__device__ __forceinline__ ull fma2(ull a, ull b, ull c) {
    ull d; asm("fma.rn.f32x2 %0, %1, %2, %3;" : "=l"(d) : "l"(a), "l"(b), "l"(c));
    return d;
}
__device__ __forceinline__ ull add2(ull a, ull b) {
    ull d; asm("add.rn.f32x2 %0, %1, %2;" : "=l"(d) : "l"(a), "l"(b));
    return d;
}
__device__ __forceinline__ float sigf(float v) { return 1.0f / (1.0f + expf(-v)); }

// ------------------------- cp.async helpers ----------------------------------
__device__ __forceinline__ void cpa16(float* smem_dst, const float* gmem_src) {
    unsigned s = (unsigned)__cvta_generic_to_shared(smem_dst);
    asm volatile("cp.async.cg.shared.global [%0], [%1], 16;" :: "r"(s), "l"(gmem_src));
}
#define CP_COMMIT() asm volatile("cp.async.commit_group;" ::: "memory")
#define CP_WAIT1()  asm volatile("cp.async.wait_group 1;" ::: "memory")
#define CP_WAIT0()  asm volatile("cp.async.wait_group 0;" ::: "memory")

// ------------------------- grid barrier (proven in R5/R8) --------------------
__device__ __forceinline__ unsigned gen_read() {
    unsigned v;
    asm volatile("ld.acquire.gpu.u32 %0, [%1];" : "=r"(v) : "l"(&g_bar_gen) : "memory");
    return v;
}
__device__ __forceinline__ void grid_barrier() {
    __syncthreads();
    if (threadIdx.x == 0) {
        unsigned target = gen_read() + 1u;          // read BEFORE arriving
        __threadfence();
        unsigned old = atomicAdd(&g_bar_count, 1u);
        if (old == NCTA - 1u) {
            atomicExch(&g_bar_count, 0u);
            __threadfence();
            atomicExch(&g_bar_gen, target);         // publish release
        } else {
            while ((int)(gen_read() - target) < 0) { __nanosleep(32); }
        }
        __threadfence();
    }
    __syncthreads();
}

// ------------------------- transpose x[B][S][D] -> xT[S][D][B] ---------------
__global__ void transpose_kernel(const float* __restrict__ x) {
    int idx = blockIdx.x * 256 + threadIdx.x;
    if (idx < S_LEN * D_IN * B_SZ) {
        int b = idx & (B_SZ - 1);
        int sd = idx >> 7;
        int d = sd & (D_IN - 1);
        int s = sd >> 6;
        g_xT[idx] = x[((size_t)b * S_LEN + s) * D_IN + d];
    }
}

// ------------------------- persistent LSTM layer -----------------------------
// CTA = 8 h-cols x 64 batches -> 32 gate rows. Weights in SMEM [j][k][4 gates].
// 256 threads = 8 warps = 2 k-teams x 4 warps. Thread: 2 batches x 2 h-cols.
// Team 0 does the first half of each chunk's k, team 1 the second half;
// partial gate sums are reduced through SMEM once per step.
template <int KIN, int CHUNKT>
__global__ __launch_bounds__(256, 1) void lstm_kernel(
    const float* __restrict__ W_ih, const float* __restrict__ W_hh,
    const float* __restrict__ b_ih, const float* __restrict__ b_hh)
{
    constexpr int K = KIN + H_SZ;
    constexpr int NCH = K / CHUNKT;
    constexpr int HALF = CHUNKT / 2;
    static_assert(K % CHUNKT == 0, "chunking");
    static_assert(KIN % CHUNKT == 0, "x/h split must align to chunks");
    extern __shared__ float wsm[];                 // [8 j][K][4 t]
    float* vbuf = wsm + 32 * K;                    // 2 x [CHUNKT][64]
    __shared__ float bsm[32];                      // [j][4 t]

    const float* inSeq = (KIN == D_IN) ? g_xT : g_h1;
    float* outSeq      = (KIN == D_IN) ? g_h1 : g_h2;

    const int tid = threadIdx.x;
    const int cid = blockIdx.x;
    const int hg = cid >> 1;
    const int bg = cid & 1;
    const int hi0 = hg * 8;
    const int bbase = bg * 64;

    // weights: gate row r = t*H + hi0 + j, element k -> wsm[(j*K + k)*4 + t]
    for (int idx = tid; idx < 32 * K; idx += 256) {
        int row = idx / K;              // row = t*8 + j
        int k = idx - row * K;
        int t = row >> 3, j = row & 7;
        int r = t * H_SZ + hi0 + j;
        float w = (k < KIN) ? W_ih[(size_t)r * KIN + k]
                            : W_hh[(size_t)r * H_SZ + (k - KIN)];
        wsm[((size_t)j * K + k) * 4 + t] = w;
    }
    if (tid < 32) {
        int t = tid >> 3, j = tid & 7;
        int r = t * H_SZ + hi0 + j;
        bsm[j * 4 + t] = b_ih[r] + b_hh[r];
    }

    const int w    = tid >> 5;          // warp 0..7
    const int team = w >> 2;            // 0 or 1 (k-halves)
    const int jp   = w & 3;             // j-pair index 0..3
    const int lane = tid & 31;
    const int j0 = jp * 2, j1 = j0 + 1;
    const int b0 = bbase + lane * 2;    // 2 batches per thread
    const int p  = jp * 32 + lane;      // team-partner index 0..127

    if (tid < 64) {                      // zero our h-slice rows (8 cols x 64 b)
        for (int jj = 0; jj < 8; ++jj)
            g_hbuf[0][(hi0 + jj) * B_SZ + bbase + tid] = 0.f;
    }

    // prefetch chunk 0 of step 0 (x-part: does not depend on h)
    {
        const float* src = inSeq + (size_t)0 * KIN * B_SZ + bbase;
        for (int op = tid; op < CHUNKT * 16; op += 256) {
            int row = op >> 4, seg = op & 15;
            cpa16(vbuf + row * 64 + seg * 4, src + (size_t)row * B_SZ + seg * 4);
        }
        CP_COMMIT();
    }
    __syncthreads();
    grid_barrier();

    // biases only in team 0's accumulators (team 1 starts at zero)
    ull bif0 = 0, bgo0 = 0, bif1 = 0, bgo1 = 0;
    if (team == 0) {
        bif0 = pk2(bsm[j0 * 4 + 0], bsm[j0 * 4 + 1]);
        bgo0 = pk2(bsm[j0 * 4 + 2], bsm[j0 * 4 + 3]);
        bif1 = pk2(bsm[j1 * 4 + 0], bsm[j1 * 4 + 1]);
        bgo1 = pk2(bsm[j1 * 4 + 2], bsm[j1 * 4 + 3]);
    }

    float c00 = 0.f, c01 = 0.f, c10 = 0.f, c11 = 0.f;   // c[j][batch]
    const float* wj0 = wsm + (size_t)j0 * K * 4;
    const float* wj1 = wsm + (size_t)j1 * K * 4;
    int nb = 1;                                    // next buffer to fill

    for (int st = 0; st < S_LEN; ++st) {
        const float* hprev = g_hbuf[st & 1];
        float* hOut = g_hbuf[(st + 1) & 1];

        // accums: a{if,go}{j}{batch}  (f32x2 over gate pairs)
        ull aif00 = bif0, ago00 = bgo0, aif01 = bif0, ago01 = bgo0;
        ull aif10 = bif1, ago10 = bgo1, aif11 = bif1, ago11 = bgo1;

        float* redbuf = vbuf;                      // set each chunk; last = scratch

        for (int ci = 0; ci < NCH; ++ci) {
            // issue next chunk
            bool issued = true;
            const float* src;
            if (ci + 1 < NCH) {
                int k0 = (ci + 1) * CHUNKT;
                src = (k0 < KIN) ? inSeq + ((size_t)st * KIN + k0) * B_SZ + bbase
                                 : hprev + (size_t)(k0 - KIN) * B_SZ + bbase;
            } else if (st + 1 < S_LEN) {
                src = inSeq + (size_t)(st + 1) * KIN * B_SZ + bbase;  // x-part
            } else {
                issued = false; src = 0;
            }
            if (issued) {
                float* dst = vbuf + nb * (CHUNKT * 64);
                for (int op = tid; op < CHUNKT * 16; op += 256) {
                    int row = op >> 4, seg = op & 15;
                    cpa16(dst + row * 64 + seg * 4, src + (size_t)row * B_SZ + seg * 4);
                }
                CP_COMMIT();
                nb ^= 1;
            }
            if (issued) CP_WAIT1(); else CP_WAIT0();
            __syncthreads();

            // compute on the READY buffer (nb if just toggled, nb^1 otherwise)
            float* cur = vbuf + (issued ? nb : (nb ^ 1)) * (CHUNKT * 64);
            redbuf = cur;
            const float* curT = cur + team * (HALF * 64);
            const ulonglong2* wk0 =
                (const ulonglong2*)(wj0 + (size_t)(ci * CHUNKT + team * HALF) * 4);
            const ulonglong2* wk1 =
                (const ulonglong2*)(wj1 + (size_t)(ci * CHUNKT + team * HALF) * 4);
#pragma unroll 8
            for (int kk = 0; kk < HALF; ++kk) {
                float2 v = *(const float2*)(curT + kk * 64 + lane * 2);
                ull v0 = dup2(v.x), v1 = dup2(v.y);
                ulonglong2 w20 = wk0[kk];          // j0: (wi,wf),(wg,wo)
                ulonglong2 w21 = wk1[kk];          // j1
                aif00 = fma2(w20.x, v0, aif00);
                ago00 = fma2(w20.y, v0, ago00);
                aif01 = fma2(w20.x, v1, aif01);
                ago01 = fma2(w20.y, v1, ago01);
                aif10 = fma2(w21.x, v0, aif10);
                ago10 = fma2(w21.y, v0, ago10);
                aif11 = fma2(w21.x, v1, aif11);
                ago11 = fma2(w21.y, v1, ago11);
            }
            __syncthreads();
        }

        // cross-team reduction through the last compute buffer (16B-aligned)
        ulonglong2* rb = (ulonglong2*)redbuf;
        if (team == 1) {
            rb[p * 4 + 0] = make_ulonglong2(aif00, ago00);
            rb[p * 4 + 1] = make_ulonglong2(aif01, ago01);
            rb[p * 4 + 2] = make_ulonglong2(aif10, ago10);
            rb[p * 4 + 3] = make_ulonglong2(aif11, ago11);
        }
        __syncthreads();
        if (team == 0) {
            ulonglong2 r0 = rb[p * 4 + 0], r1 = rb[p * 4 + 1];
            ulonglong2 r2 = rb[p * 4 + 2], r3 = rb[p * 4 + 3];
            aif00 = add2(aif00, r0.x); ago00 = add2(ago00, r0.y);
            aif01 = add2(aif01, r1.x); ago01 = add2(ago01, r1.y);
            aif10 = add2(aif10, r2.x); ago10 = add2(ago10, r2.y);
            aif11 = add2(aif11, r3.x); ago11 = add2(ago11, r3.y);

            float gi, gf, gg, go;
            // j0, batch0
            unpk(aif00, gi, gf); float gg0t, go0t; unpk(ago00, gg0t, go0t);
            float cn = sigf(gf) * c00 + sigf(gi) * tanhf(gg0t);
            float h00 = sigf(go0t) * tanhf(cn); c00 = cn;
            // j0, batch1
            unpk(aif01, gi, gf); unpk(ago01, gg, go);
            cn = sigf(gf) * c01 + sigf(gi) * tanhf(gg);
            float h01 = sigf(go) * tanhf(cn); c01 = cn;
            // j1, batch0
            unpk(aif10, gi, gf); unpk(ago10, gg, go);
            cn = sigf(gf) * c10 + sigf(gi) * tanhf(gg);
            float h10 = sigf(go) * tanhf(cn); c10 = cn;
            // j1, batch1
            unpk(aif11, gi, gf); unpk(ago11, gg, go);
            cn = sigf(gf) * c11 + sigf(gi) * tanhf(gg);
            float h11 = sigf(go) * tanhf(cn); c11 = cn;

            float2 hv0 = make_float2(h00, h01);
            float2 hv1 = make_float2(h10, h11);
            *(float2*)&hOut[(hi0 + j0) * B_SZ + b0] = hv0;
            *(float2*)&hOut[(hi0 + j1) * B_SZ + b0] = hv1;
            float* o = outSeq + (size_t)st * H_SZ * B_SZ;
            *(float2*)&o[(size_t)(hi0 + j0) * B_SZ + b0] = hv0;
            *(float2*)&o[(size_t)(hi0 + j1) * B_SZ + b0] = hv1;
        }

        grid_barrier();
    }
}

// ------------------------- attention energies --------------------------------
__global__ __launch_bounds__(256) void energy_kernel(
    const float* __restrict__ Wa, const float* __restrict__ ba,
    const float* __restrict__ va, const float* __restrict__ bv)
{
    const int s = blockIdx.x;
    const int tid = threadIdx.x;
    const int tx = tid & 15, ty = tid >> 4;
    __shared__ float sWa[32][132];
    __shared__ float sIn[32][132];
    __shared__ float red[16][128];
    const float* h2s = g_h2 + (size_t)s * H_SZ * B_SZ;

    float epart[8];
#pragma unroll
    for (int q = 0; q < 8; ++q) epart[q] = 0.f;

    for (int gc = 0; gc < 4; ++gc) {
        const int g0 = gc * 128;
        float acc[8][8];
#pragma unroll
        for (int i = 0; i < 8; ++i)
#pragma unroll
            for (int q = 0; q < 8; ++q) acc[i][q] = 0.f;

        for (int kt = 0; kt < 16; ++kt) {
            const int k0 = kt * 32;
            __syncthreads();
            for (int idx = tid; idx < 4096; idx += 256) {
                int gg = idx >> 5, kk = idx & 31;
                sWa[kk][gg] = Wa[(size_t)(g0 + gg) * H_SZ + k0 + kk];
            }
            for (int idx = tid; idx < 4096; idx += 256) {
                int kk = idx >> 7, bb = idx & 127;
                sIn[kk][bb] = h2s[(size_t)(k0 + kk) * B_SZ + bb];
            }
            __syncthreads();
#pragma unroll 4
            for (int k = 0; k < 32; ++k) {
                float4 w0 = *(float4*)&sWa[k][tx * 8];
                float4 w1 = *(float4*)&sWa[k][tx * 8 + 4];
                float4 i0 = *(float4*)&sIn[k][ty * 8];
                float4 i1 = *(float4*)&sIn[k][ty * 8 + 4];
                float wv[8] = {w0.x, w0.y, w0.z, w0.w, w1.x, w1.y, w1.z, w1.w};
                float iv[8] = {i0.x, i0.y, i0.z, i0.w, i1.x, i1.y, i1.z, i1.w};
#pragma unroll
                for (int i = 0; i < 8; ++i)
#pragma unroll
                    for (int q = 0; q < 8; ++q) acc[i][q] += wv[i] * iv[q];
            }
        }
#pragma unroll
        for (int i = 0; i < 8; ++i) {
            int gidx = g0 + tx * 8 + i;
            float gv = va[gidx], bav = ba[gidx];
#pragma unroll
            for (int q = 0; q < 8; ++q) epart[q] += gv * tanhf(acc[i][q] + bav);
        }
    }
    __syncthreads();
#pragma unroll
    for (int q = 0; q < 8; ++q) red[tx][ty * 8 + q] = epart[q];
    __syncthreads();
    if (tid < 128) {
        float e = bv[0];
#pragma unroll
        for (int t = 0; t < 16; ++t) e += red[t][tid];
        g_e[(size_t)tid * S_LEN + s] = e;
    }
}

// ------------------------- entmax15 (faithful to reference) ------------------
__global__ __launch_bounds__(512) void entmax_kernel(float* __restrict__ dout)
{
    const int b = blockIdx.x;
    const int tid = threadIdx.x;
    __shared__ float xs[1024], xo[1024], sa[1024], sb[1024];
    __shared__ float rf[512];
    __shared__ int ri[512];
    const float* row = g_e + (size_t)b * S_LEN;

    xo[tid] = row[tid];
    xo[tid + 512] = row[tid + 512];
    __syncthreads();
    rf[tid] = fmaxf(xo[tid], xo[tid + 512]);
    __syncthreads();
    for (int off = 256; off > 0; off >>= 1) {
        if (tid < off) rf[tid] = fmaxf(rf[tid], rf[tid + off]);
        __syncthreads();
    }
    float mx = rf[0];
    __syncthreads();
    xo[tid] -= mx; xo[tid + 512] -= mx;
    xs[tid] = xo[tid]; xs[tid + 512] = xo[tid + 512];
    __syncthreads();

    for (int k = 2; k <= 1024; k <<= 1) {
        for (int jj = k >> 1; jj > 0; jj >>= 1) {
            for (int i = tid; i < 1024; i += 512) {
                int ixj = i ^ jj;
                if (ixj > i) {
                    bool up = ((i & k) == 0);
                    float a = xs[i], c2 = xs[ixj];
                    bool sw = up ? (a < c2) : (a > c2);
                    if (sw) { xs[i] = c2; xs[ixj] = a; }
                }
            }
            __syncthreads();
        }
    }

    sa[tid] = xs[tid]; sa[tid + 512] = xs[tid + 512];
    __syncthreads();
    float* pa = sa; float* pb = sb;
    for (int off = 1; off < 1024; off <<= 1) {
        for (int i = tid; i < 1024; i += 512)
            pb[i] = pa[i] + ((i >= off) ? pa[i - off] : 0.f);
        __syncthreads();
        float* t = pa; pa = pb; pb = t;
    }

    int cnt = 0;
    for (int i = tid; i < 1024; i += 512) {
        float sup = (float)(i + 1) * xs[i] - pa[i] + 0.5f;
        if (sup > 0.f) cnt++;
    }
    ri[tid] = cnt;
    __syncthreads();
    for (int off = 256; off > 0; off >>= 1) {
        if (tid < off) ri[tid] += ri[tid + off];
        __syncthreads();
    }
    int ssize = ri[0];
    if (ssize < 1) ssize = 1;
    if (ssize > 1023) ssize = 1023;
    float tau = ((float)(ssize + 1) * xs[ssize] - pa[ssize] + 0.5f) / (float)(ssize + 1);

    float d0 = xo[tid] - tau;
    float d1 = xo[tid + 512] - tau;
    float y0 = d0 > 0.f ? sqrtf(d0) : 0.f;
    float y1 = d1 > 0.f ? sqrtf(d1) : 0.f;
    __syncthreads();
    rf[tid] = y0 + y1;
    __syncthreads();
    for (int off = 256; off > 0; off >>= 1) {
        if (tid < off) rf[tid] += rf[tid + off];
        __syncthreads();
    }
    float inv = 1.f / rf[0];
    float w0 = y0 * inv, w1 = y1 * inv;
    g_att[(size_t)b * S_LEN + tid] = w0;
    g_att[(size_t)b * S_LEN + tid + 512] = w1;
    dout[128 + (size_t)b * S_LEN + tid] = w0;
    dout[128 + (size_t)b * S_LEN + tid + 512] = w1;
}

// ------------------------- context stage 1 -----------------------------------
__global__ __launch_bounds__(256) void ctx1_kernel()
{
    __shared__ float sAtt[64 * 128];
    const int bid = blockIdx.x;
    const int ch = bid >> 2, hq = bid & 3;
    const int s0 = ch * 64, h0 = hq * 128;
    const int tid = threadIdx.x;

    for (int idx = tid; idx < 64 * 128; idx += 256) {
        int sl = idx >> 7, bb = idx & 127;
        sAtt[idx] = g_att[(size_t)bb * S_LEN + s0 + sl];
    }
    __syncthreads();

    float racc[64];
#pragma unroll
    for (int u = 0; u < 64; ++u) racc[u] = 0.f;

    const int bcol = tid & 127;
    for (int sl = 0; sl < 64; ++sl) {
        const float* src = g_h2 + ((size_t)(s0 + sl) * H_SZ + h0) * B_SZ;
        float av = sAtt[sl * 128 + bcol];
#pragma unroll 8
        for (int u = 0; u < 64; ++u)
            racc[u] += av * __ldg(src + tid + u * 256);
    }
#pragma unroll
    for (int u = 0; u < 64; ++u)
        g_pc[(size_t)bid * 16384 + tid + u * 256] = racc[u];
}

// ------------------------- context stage 2 + FC ------------------------------
__global__ void ctx2_kernel()
{
    int e = blockIdx.x * 256 + threadIdx.x;
    if (e < H_SZ * B_SZ) {
        int h = e >> 7, bb = e & 127;
        int hq = h >> 7, hl = h & 127;
        float s = 0.f;
#pragma unroll
        for (int ch = 0; ch < 16; ++ch)
            s += g_pc[((size_t)(ch * 4 + hq) * 16384) + hl * 128 + bb];
        g_ctx[e] = s;
    }
}

__global__ void fc_kernel(const float* __restrict__ fcW,
                          const float* __restrict__ fcb,
                          float* __restrict__ out)
{
    int b = threadIdx.x;
    float a = fcb[0];
    for (int h = 0; h < H_SZ; ++h) a += fcW[h] * g_ctx[h * B_SZ + b];
    out[b] = a;
}

// ------------------------- launch --------------------------------------------
extern "C" void kernel_launch(void* const* d_in, const int* in_sizes, int n_in,
                              void* d_out, int out_size)
{
    (void)in_sizes; (void)n_in; (void)out_size;
    const float* x     = (const float*)d_in[0];
    const float* W_ih0 = (const float*)d_in[1];
    const float* W_hh0 = (const float*)d_in[2];
    const float* b_ih0 = (const float*)d_in[3];
    const float* b_hh0 = (const float*)d_in[4];
    const float* W_ih1 = (const float*)d_in[5];
    const float* W_hh1 = (const float*)d_in[6];
    const float* b_ih1 = (const float*)d_in[7];
    const float* b_hh1 = (const float*)d_in[8];
    const float* W_a   = (const float*)d_in[9];
    const float* b_a   = (const float*)d_in[10];
    const float* v_a   = (const float*)d_in[11];
    const float* b_v   = (const float*)d_in[12];
    const float* fc_W  = (const float*)d_in[13];
    const float* fc_b  = (const float*)d_in[14];
    float* out = (float*)d_out;

    const int smem0 = (32 * (D_IN + H_SZ) + 2 * 64 * 64) * 4;    // 106,496 B
    const int smem1 = (32 * (H_SZ + H_SZ) + 2 * 128 * 64) * 4;   // 196,608 B
    cudaFuncSetAttribute(lstm_kernel<D_IN, 64>,
                         cudaFuncAttributeMaxDynamicSharedMemorySize, smem0);
    cudaFuncSetAttribute(lstm_kernel<H_SZ, 128>,
                         cudaFuncAttributeMaxDynamicSharedMemorySize, smem1);

    transpose_kernel<<<(S_LEN * D_IN * B_SZ + 255) / 256, 256>>>(x);
    lstm_kernel<D_IN, 64><<<NCTA, 256, smem0>>>(W_ih0, W_hh0, b_ih0, b_hh0);
    lstm_kernel<H_SZ, 128><<<NCTA, 256, smem1>>>(W_ih1, W_hh1, b_ih1, b_hh1);
    energy_kernel<<<S_LEN, 256>>>(W_a, b_a, v_a, b_v);
    entmax_kernel<<<B_SZ, 512>>>(out);
    ctx1_kernel<<<64, 256>>>();
    ctx2_kernel<<<(H_SZ * B_SZ + 255) / 256, 256>>>();
    fc_kernel<<<1, 128>>>(fc_W, fc_b, out);
}

// round 12
// speedup vs baseline: 1.4873x; 1.0283x over previous
#include <cuda_runtime.h>
#include <math.h>

#define S_LEN 1024
#define B_SZ  128
#define D_IN  64
#define H_SZ  512
#define NCTA  128

typedef unsigned long long ull;

// ------------------------- device scratch (allocation-free rule) -------------
__device__ float g_xT[S_LEN * D_IN * B_SZ];                 // [S][D][B]   32 MB
__device__ float g_h1[(size_t)S_LEN * H_SZ * B_SZ];         // [S][H][B]  256 MB
__device__ float g_h2[(size_t)S_LEN * H_SZ * B_SZ];         // [S][H][B]  256 MB
__device__ float g_hbuf[2][H_SZ * B_SZ];                    // double-buffered h
__device__ float g_e[B_SZ * S_LEN];                         // energies [B][S]
__device__ float g_att[B_SZ * S_LEN];                       // entmax weights
__device__ float g_pc[64 * 128 * 128];                      // partial contexts
__device__ float g_ctx[H_SZ * B_SZ];                        // context [H][B]
__device__ unsigned g_bar_count;
__device__ unsigned g_bar_gen;

// ------------------------- f32x2 helpers -------------------------------------
__device__ __forceinline__ ull dup2(float v) {
    ull r; asm("mov.b64 %0, {%1, %1};" : "=l"(r) : "f"(v)); return r;
}
__device__ __forceinline__ ull pk2(float lo, float hi) {
    ull r; asm("mov.b64 %0, {%1, %2};" : "=l"(r) : "f"(lo), "f"(hi)); return r;
}
__device__ __forceinline__ void unpk(ull v, float& lo, float& hi) {
    asm("mov.b64 {%0, %1}, %2;" : "=f"(lo), "=f"(hi) : "l"(v));
}
__device__ __forceinline__ ull fma2(ull a, ull b, ull c) {
    ull d; asm("fma.rn.f32x2 %0, %1, %2, %3;" : "=l"(d) : "l"(a), "l"(b), "l"(c));
    return d;
}
__device__ __forceinline__ ull add2(ull a, ull b) {
    ull d; asm("add.rn.f32x2 %0, %1, %2;" : "=l"(d) : "l"(a), "l"(b));
    return d;
}
__device__ __forceinline__ float sigf(float v) { return 1.0f / (1.0f + expf(-v)); }

// ------------------------- cp.async helpers ----------------------------------
__device__ __forceinline__ void cpa16(float* smem_dst, const float* gmem_src) {
    unsigned s = (unsigned)__cvta_generic_to_shared(smem_dst);
    asm volatile("cp.async.cg.shared.global [%0], [%1], 16;" :: "r"(s), "l"(gmem_src));
}
#define CP_COMMIT() asm volatile("cp.async.commit_group;" ::: "memory")
#define CP_WAIT1()  asm volatile("cp.async.wait_group 1;" ::: "memory")
#define CP_WAIT0()  asm volatile("cp.async.wait_group 0;" ::: "memory")

// ------------------------- split grid barrier (arrive / wait) ----------------
// Same proven R5/R8 protocol, phase-split. Every CTA: one arrive + one wait
// per generation. Count self-resets on release.
__device__ __forceinline__ unsigned gen_read() {
    unsigned v;
    asm volatile("ld.acquire.gpu.u32 %0, [%1];" : "=r"(v) : "l"(&g_bar_gen) : "memory");
    return v;
}
__device__ __forceinline__ void bar_arrive(unsigned& tgt) {
    __syncthreads();                                // all CTA writes done
    if (threadIdx.x == 0) {
        tgt = gen_read() + 1u;                      // read BEFORE arriving
        __threadfence();
        unsigned old = atomicAdd(&g_bar_count, 1u);
        if (old == NCTA - 1u) {
            atomicExch(&g_bar_count, 0u);
            __threadfence();
            atomicExch(&g_bar_gen, tgt);            // publish release
        }
    }
}
__device__ __forceinline__ void bar_wait(unsigned tgt) {
    if (threadIdx.x == 0) {
        while ((int)(gen_read() - tgt) < 0) { __nanosleep(32); }
        __threadfence();
    }
    __syncthreads();
}

// ------------------------- transpose x[B][S][D] -> xT[S][D][B] ---------------
__global__ void transpose_kernel(const float* __restrict__ x) {
    int idx = blockIdx.x * 256 + threadIdx.x;
    if (idx < S_LEN * D_IN * B_SZ) {
        int b = idx & (B_SZ - 1);
        int sd = idx >> 7;
        int d = sd & (D_IN - 1);
        int s = sd >> 6;
        g_xT[idx] = x[((size_t)b * S_LEN + s) * D_IN + d];
    }
}

// ------------------------- persistent LSTM layer -----------------------------
// CTA = 8 h-cols x 64 batches -> 32 gate rows. Weights in SMEM [j][k][4 gates].
// 256 threads = 2 k-teams x 4 warps; thread: 2 batches x 2 h-cols (R11 proven).
// NEW: split barrier — arrive after writing h, wait only before the first
// h-chunk copy of the next step; x-part chunks overlap the barrier.
template <int KIN, int CHUNKT>
__global__ __launch_bounds__(256, 1) void lstm_kernel(
    const float* __restrict__ W_ih, const float* __restrict__ W_hh,
    const float* __restrict__ b_ih, const float* __restrict__ b_hh)
{
    constexpr int K = KIN + H_SZ;
    constexpr int NCH = K / CHUNKT;
    constexpr int NCHX = KIN / CHUNKT;             // x-part chunk count (>=1)
    constexpr int HALF = CHUNKT / 2;
    static_assert(K % CHUNKT == 0, "chunking");
    static_assert(KIN % CHUNKT == 0, "x/h split must align to chunks");
    extern __shared__ float wsm[];                 // [8 j][K][4 t]
    float* vbuf = wsm + 32 * K;                    // 2 x [CHUNKT][64]
    __shared__ float bsm[32];                      // [j][4 t]

    const float* inSeq = (KIN == D_IN) ? g_xT : g_h1;
    float* outSeq      = (KIN == D_IN) ? g_h1 : g_h2;

    const int tid = threadIdx.x;
    const int cid = blockIdx.x;
    const int hg = cid >> 1;
    const int bg = cid & 1;
    const int hi0 = hg * 8;
    const int bbase = bg * 64;

    // weights: gate row r = t*H + hi0 + j, element k -> wsm[(j*K + k)*4 + t]
    for (int idx = tid; idx < 32 * K; idx += 256) {
        int row = idx / K;              // row = t*8 + j
        int k = idx - row * K;
        int t = row >> 3, j = row & 7;
        int r = t * H_SZ + hi0 + j;
        float w = (k < KIN) ? W_ih[(size_t)r * KIN + k]
                            : W_hh[(size_t)r * H_SZ + (k - KIN)];
        wsm[((size_t)j * K + k) * 4 + t] = w;
    }
    if (tid < 32) {
        int t = tid >> 3, j = tid & 7;
        int r = t * H_SZ + hi0 + j;
        bsm[j * 4 + t] = b_ih[r] + b_hh[r];
    }

    const int w    = tid >> 5;          // warp 0..7
    const int team = w >> 2;            // 0 or 1 (k-halves)
    const int jp   = w & 3;             // j-pair index 0..3
    const int lane = tid & 31;
    const int j0 = jp * 2, j1 = j0 + 1;
    const int b0 = bbase + lane * 2;    // 2 batches per thread
    const int p  = jp * 32 + lane;      // team-partner index 0..127

    if (tid < 64) {                      // zero our h-slice rows (8 cols x 64 b)
        for (int jj = 0; jj < 8; ++jj)
            g_hbuf[0][(hi0 + jj) * B_SZ + bbase + tid] = 0.f;
    }

    // prefetch chunk 0 of step 0 (x-part: does not depend on h)
    {
        const float* src = inSeq + (size_t)0 * KIN * B_SZ + bbase;
        for (int op = tid; op < CHUNKT * 16; op += 256) {
            int row = op >> 4, seg = op & 15;
            cpa16(vbuf + row * 64 + seg * 4, src + (size_t)row * B_SZ + seg * 4);
        }
        CP_COMMIT();
    }

    unsigned bar_tgt = 0;
    bar_arrive(bar_tgt);                 // covers h-zero init; step 0 waits it

    // biases only in team 0's accumulators (team 1 starts at zero)
    ull bif0 = 0, bgo0 = 0, bif1 = 0, bgo1 = 0;
    if (team == 0) {
        bif0 = pk2(bsm[j0 * 4 + 0], bsm[j0 * 4 + 1]);
        bgo0 = pk2(bsm[j0 * 4 + 2], bsm[j0 * 4 + 3]);
        bif1 = pk2(bsm[j1 * 4 + 0], bsm[j1 * 4 + 1]);
        bgo1 = pk2(bsm[j1 * 4 + 2], bsm[j1 * 4 + 3]);
    }

    float c00 = 0.f, c01 = 0.f, c10 = 0.f, c11 = 0.f;   // c[j][batch]
    const float* wj0 = wsm + (size_t)j0 * K * 4;
    const float* wj1 = wsm + (size_t)j1 * K * 4;
    int cb = 0;                                    // buffer holding current chunk

    for (int st = 0; st < S_LEN; ++st) {
        const float* hprev = g_hbuf[st & 1];
        float* hOut = g_hbuf[(st + 1) & 1];

        // accums: a{if,go}{j}{batch}  (f32x2 over gate pairs)
        ull aif00 = bif0, ago00 = bgo0, aif01 = bif0, ago01 = bgo0;
        ull aif10 = bif1, ago10 = bgo1, aif11 = bif1, ago11 = bgo1;

        int last_cb = cb;

        auto compute_chunk = [&](int ci, int cbuf) {
            const float* curT = vbuf + cbuf * (CHUNKT * 64) + team * (HALF * 64);
            const ulonglong2* wk0 =
                (const ulonglong2*)(wj0 + (size_t)(ci * CHUNKT + team * HALF) * 4);
            const ulonglong2* wk1 =
                (const ulonglong2*)(wj1 + (size_t)(ci * CHUNKT + team * HALF) * 4);
#pragma unroll 8
            for (int kk = 0; kk < HALF; ++kk) {
                float2 v = *(const float2*)(curT + kk * 64 + lane * 2);
                ull v0 = dup2(v.x), v1 = dup2(v.y);
                ulonglong2 w20 = wk0[kk];
                ulonglong2 w21 = wk1[kk];
                aif00 = fma2(w20.x, v0, aif00);
                ago00 = fma2(w20.y, v0, ago00);
                aif01 = fma2(w20.x, v1, aif01);
                ago01 = fma2(w20.y, v1, ago01);
                aif10 = fma2(w21.x, v0, aif10);
                ago10 = fma2(w21.y, v0, ago10);
                aif11 = fma2(w21.x, v1, aif11);
                ago11 = fma2(w21.y, v1, ago11);
            }
        };

        auto issue_copy = [&](const float* src, int dbuf) {
            float* dst = vbuf + dbuf * (CHUNKT * 64);
            for (int op = tid; op < CHUNKT * 16; op += 256) {
                int row = op >> 4, seg = op & 15;
                cpa16(dst + row * 64 + seg * 4, src + (size_t)row * B_SZ + seg * 4);
            }
            CP_COMMIT();
        };

        for (int ci = 0; ci < NCH; ++ci) {
            // source of NEXT chunk
            const float* src = 0;
            bool has_next = true;
            if (ci + 1 < NCH) {
                int k0 = (ci + 1) * CHUNKT;
                src = (k0 < KIN) ? inSeq + ((size_t)st * KIN + k0) * B_SZ + bbase
                                 : hprev + (size_t)(k0 - KIN) * B_SZ + bbase;
            } else if (st + 1 < S_LEN) {
                src = inSeq + (size_t)(st + 1) * KIN * B_SZ + bbase;  // x-part
            } else {
                has_next = false;
            }

            if (ci == NCHX - 1) {
                // transition: compute current (x) chunk first, then wait the
                // barrier, then issue the first h-chunk copy.
                CP_WAIT0();
                __syncthreads();
                compute_chunk(ci, cb);
                __syncthreads();
                bar_wait(bar_tgt);                 // h of step st now published
                issue_copy(src, cb ^ 1);           // first h chunk
                last_cb = cb;
                cb ^= 1;
            } else {
                if (has_next) issue_copy(src, cb ^ 1);
                if (has_next) CP_WAIT1(); else CP_WAIT0();
                __syncthreads();
                compute_chunk(ci, cb);
                __syncthreads();
                last_cb = cb;
                if (has_next) cb ^= 1;
            }
        }

        // cross-team reduction through the last computed buffer (16B-aligned)
        ulonglong2* rb = (ulonglong2*)(vbuf + last_cb * (CHUNKT * 64));
        if (team == 1) {
            rb[p * 4 + 0] = make_ulonglong2(aif00, ago00);
            rb[p * 4 + 1] = make_ulonglong2(aif01, ago01);
            rb[p * 4 + 2] = make_ulonglong2(aif10, ago10);
            rb[p * 4 + 3] = make_ulonglong2(aif11, ago11);
        }
        __syncthreads();
        if (team == 0) {
            ulonglong2 r0 = rb[p * 4 + 0], r1 = rb[p * 4 + 1];
            ulonglong2 r2 = rb[p * 4 + 2], r3 = rb[p * 4 + 3];
            aif00 = add2(aif00, r0.x); ago00 = add2(ago00, r0.y);
            aif01 = add2(aif01, r1.x); ago01 = add2(ago01, r1.y);
            aif10 = add2(aif10, r2.x); ago10 = add2(ago10, r2.y);
            aif11 = add2(aif11, r3.x); ago11 = add2(ago11, r3.y);

            float gi, gf, gg, go;
            unpk(aif00, gi, gf); float gg0t, go0t; unpk(ago00, gg0t, go0t);
            float cn = sigf(gf) * c00 + sigf(gi) * tanhf(gg0t);
            float h00 = sigf(go0t) * tanhf(cn); c00 = cn;
            unpk(aif01, gi, gf); unpk(ago01, gg, go);
            cn = sigf(gf) * c01 + sigf(gi) * tanhf(gg);
            float h01 = sigf(go) * tanhf(cn); c01 = cn;
            unpk(aif10, gi, gf); unpk(ago10, gg, go);
            cn = sigf(gf) * c10 + sigf(gi) * tanhf(gg);
            float h10 = sigf(go) * tanhf(cn); c10 = cn;
            unpk(aif11, gi, gf); unpk(ago11, gg, go);
            cn = sigf(gf) * c11 + sigf(gi) * tanhf(gg);
            float h11 = sigf(go) * tanhf(cn); c11 = cn;

            float2 hv0 = make_float2(h00, h01);
            float2 hv1 = make_float2(h10, h11);
            *(float2*)&hOut[(hi0 + j0) * B_SZ + b0] = hv0;
            *(float2*)&hOut[(hi0 + j1) * B_SZ + b0] = hv1;
            float* o = outSeq + (size_t)st * H_SZ * B_SZ;
            *(float2*)&o[(size_t)(hi0 + j0) * B_SZ + b0] = hv0;
            *(float2*)&o[(size_t)(hi0 + j1) * B_SZ + b0] = hv1;
        }

        bar_arrive(bar_tgt);   // non-blocking; next step's x-part overlaps it
    }
}

// ------------------------- attention energies --------------------------------
__global__ __launch_bounds__(256) void energy_kernel(
    const float* __restrict__ Wa, const float* __restrict__ ba,
    const float* __restrict__ va, const float* __restrict__ bv)
{
    const int s = blockIdx.x;
    const int tid = threadIdx.x;
    const int tx = tid & 15, ty = tid >> 4;
    __shared__ float sWa[32][132];
    __shared__ float sIn[32][132];
    __shared__ float red[16][128];
    const float* h2s = g_h2 + (size_t)s * H_SZ * B_SZ;

    float epart[8];
#pragma unroll
    for (int q = 0; q < 8; ++q) epart[q] = 0.f;

    for (int gc = 0; gc < 4; ++gc) {
        const int g0 = gc * 128;
        float acc[8][8];
#pragma unroll
        for (int i = 0; i < 8; ++i)
#pragma unroll
            for (int q = 0; q < 8; ++q) acc[i][q] = 0.f;

        for (int kt = 0; kt < 16; ++kt) {
            const int k0 = kt * 32;
            __syncthreads();
            for (int idx = tid; idx < 4096; idx += 256) {
                int gg = idx >> 5, kk = idx & 31;
                sWa[kk][gg] = Wa[(size_t)(g0 + gg) * H_SZ + k0 + kk];
            }
            for (int idx = tid; idx < 4096; idx += 256) {
                int kk = idx >> 7, bb = idx & 127;
                sIn[kk][bb] = h2s[(size_t)(k0 + kk) * B_SZ + bb];
            }
            __syncthreads();
#pragma unroll 4
            for (int k = 0; k < 32; ++k) {
                float4 w0 = *(float4*)&sWa[k][tx * 8];
                float4 w1 = *(float4*)&sWa[k][tx * 8 + 4];
                float4 i0 = *(float4*)&sIn[k][ty * 8];
                float4 i1 = *(float4*)&sIn[k][ty * 8 + 4];
                float wv[8] = {w0.x, w0.y, w0.z, w0.w, w1.x, w1.y, w1.z, w1.w};
                float iv[8] = {i0.x, i0.y, i0.z, i0.w, i1.x, i1.y, i1.z, i1.w};
#pragma unroll
                for (int i = 0; i < 8; ++i)
#pragma unroll
                    for (int q = 0; q < 8; ++q) acc[i][q] += wv[i] * iv[q];
            }
        }
#pragma unroll
        for (int i = 0; i < 8; ++i) {
            int gidx = g0 + tx * 8 + i;
            float gv = va[gidx], bav = ba[gidx];
#pragma unroll
            for (int q = 0; q < 8; ++q) epart[q] += gv * tanhf(acc[i][q] + bav);
        }
    }
    __syncthreads();
#pragma unroll
    for (int q = 0; q < 8; ++q) red[tx][ty * 8 + q] = epart[q];
    __syncthreads();
    if (tid < 128) {
        float e = bv[0];
#pragma unroll
        for (int t = 0; t < 16; ++t) e += red[t][tid];
        g_e[(size_t)tid * S_LEN + s] = e;
    }
}

// ------------------------- entmax15 (faithful to reference) ------------------
__global__ __launch_bounds__(512) void entmax_kernel(float* __restrict__ dout)
{
    const int b = blockIdx.x;
    const int tid = threadIdx.x;
    __shared__ float xs[1024], xo[1024], sa[1024], sb[1024];
    __shared__ float rf[512];
    __shared__ int ri[512];
    const float* row = g_e + (size_t)b * S_LEN;

    xo[tid] = row[tid];
    xo[tid + 512] = row[tid + 512];
    __syncthreads();
    rf[tid] = fmaxf(xo[tid], xo[tid + 512]);
    __syncthreads();
    for (int off = 256; off > 0; off >>= 1) {
        if (tid < off) rf[tid] = fmaxf(rf[tid], rf[tid + off]);
        __syncthreads();
    }
    float mx = rf[0];
    __syncthreads();
    xo[tid] -= mx; xo[tid + 512] -= mx;
    xs[tid] = xo[tid]; xs[tid + 512] = xo[tid + 512];
    __syncthreads();

    for (int k = 2; k <= 1024; k <<= 1) {
        for (int jj = k >> 1; jj > 0; jj >>= 1) {
            for (int i = tid; i < 1024; i += 512) {
                int ixj = i ^ jj;
                if (ixj > i) {
                    bool up = ((i & k) == 0);
                    float a = xs[i], c2 = xs[ixj];
                    bool sw = up ? (a < c2) : (a > c2);
                    if (sw) { xs[i] = c2; xs[ixj] = a; }
                }
            }
            __syncthreads();
        }
    }

    sa[tid] = xs[tid]; sa[tid + 512] = xs[tid + 512];
    __syncthreads();
    float* pa = sa; float* pb = sb;
    for (int off = 1; off < 1024; off <<= 1) {
        for (int i = tid; i < 1024; i += 512)
            pb[i] = pa[i] + ((i >= off) ? pa[i - off] : 0.f);
        __syncthreads();
        float* t = pa; pa = pb; pb = t;
    }

    int cnt = 0;
    for (int i = tid; i < 1024; i += 512) {
        float sup = (float)(i + 1) * xs[i] - pa[i] + 0.5f;
        if (sup > 0.f) cnt++;
    }
    ri[tid] = cnt;
    __syncthreads();
    for (int off = 256; off > 0; off >>= 1) {
        if (tid < off) ri[tid] += ri[tid + off];
        __syncthreads();
    }
    int ssize = ri[0];
    if (ssize < 1) ssize = 1;
    if (ssize > 1023) ssize = 1023;
    float tau = ((float)(ssize + 1) * xs[ssize] - pa[ssize] + 0.5f) / (float)(ssize + 1);

    float d0 = xo[tid] - tau;
    float d1 = xo[tid + 512] - tau;
    float y0 = d0 > 0.f ? sqrtf(d0) : 0.f;
    float y1 = d1 > 0.f ? sqrtf(d1) : 0.f;
    __syncthreads();
    rf[tid] = y0 + y1;
    __syncthreads();
    for (int off = 256; off > 0; off >>= 1) {
        if (tid < off) rf[tid] += rf[tid + off];
        __syncthreads();
    }
    float inv = 1.f / rf[0];
    float w0 = y0 * inv, w1 = y1 * inv;
    g_att[(size_t)b * S_LEN + tid] = w0;
    g_att[(size_t)b * S_LEN + tid + 512] = w1;
    dout[128 + (size_t)b * S_LEN + tid] = w0;
    dout[128 + (size_t)b * S_LEN + tid + 512] = w1;
}

// ------------------------- context stage 1 -----------------------------------
__global__ __launch_bounds__(256) void ctx1_kernel()
{
    __shared__ float sAtt[64 * 128];
    const int bid = blockIdx.x;
    const int ch = bid >> 2, hq = bid & 3;
    const int s0 = ch * 64, h0 = hq * 128;
    const int tid = threadIdx.x;

    for (int idx = tid; idx < 64 * 128; idx += 256) {
        int sl = idx >> 7, bb = idx & 127;
        sAtt[idx] = g_att[(size_t)bb * S_LEN + s0 + sl];
    }
    __syncthreads();

    float racc[64];
#pragma unroll
    for (int u = 0; u < 64; ++u) racc[u] = 0.f;

    const int bcol = tid & 127;
    for (int sl = 0; sl < 64; ++sl) {
        const float* src = g_h2 + ((size_t)(s0 + sl) * H_SZ + h0) * B_SZ;
        float av = sAtt[sl * 128 + bcol];
#pragma unroll 8
        for (int u = 0; u < 64; ++u)
            racc[u] += av * __ldg(src + tid + u * 256);
    }
#pragma unroll
    for (int u = 0; u < 64; ++u)
        g_pc[(size_t)bid * 16384 + tid + u * 256] = racc[u];
}

// ------------------------- context stage 2 + FC ------------------------------
__global__ void ctx2_kernel()
{
    int e = blockIdx.x * 256 + threadIdx.x;
    if (e < H_SZ * B_SZ) {
        int h = e >> 7, bb = e & 127;
        int hq = h >> 7, hl = h & 127;
        float s = 0.f;
#pragma unroll
        for (int ch = 0; ch < 16; ++ch)
            s += g_pc[((size_t)(ch * 4 + hq) * 16384) + hl * 128 + bb];
        g_ctx[e] = s;
    }
}

__global__ void fc_kernel(const float* __restrict__ fcW,
                          const float* __restrict__ fcb,
                          float* __restrict__ out)
{
    int b = threadIdx.x;
    float a = fcb[0];
    for (int h = 0; h < H_SZ; ++h) a += fcW[h] * g_ctx[h * B_SZ + b];
    out[b] = a;
}

// ------------------------- launch --------------------------------------------
extern "C" void kernel_launch(void* const* d_in, const int* in_sizes, int n_in,
                              void* d_out, int out_size)
{
    (void)in_sizes; (void)n_in; (void)out_size;
    const float* x     = (const float*)d_in[0];
    const float* W_ih0 = (const float*)d_in[1];
    const float* W_hh0 = (const float*)d_in[2];
    const float* b_ih0 = (const float*)d_in[3];
    const float* b_hh0 = (const float*)d_in[4];
    const float* W_ih1 = (const float*)d_in[5];
    const float* W_hh1 = (const float*)d_in[6];
    const float* b_ih1 = (const float*)d_in[7];
    const float* b_hh1 = (const float*)d_in[8];
    const float* W_a   = (const float*)d_in[9];
    const float* b_a   = (const float*)d_in[10];
    const float* v_a   = (const float*)d_in[11];
    const float* b_v   = (const float*)d_in[12];
    const float* fc_W  = (const float*)d_in[13];
    const float* fc_b  = (const float*)d_in[14];
    float* out = (float*)d_out;

    const int smem0 = (32 * (D_IN + H_SZ) + 2 * 64 * 64) * 4;    // 106,496 B
    const int smem1 = (32 * (H_SZ + H_SZ) + 2 * 128 * 64) * 4;   // 196,608 B
    cudaFuncSetAttribute(lstm_kernel<D_IN, 64>,
                         cudaFuncAttributeMaxDynamicSharedMemorySize, smem0);
    cudaFuncSetAttribute(lstm_kernel<H_SZ, 128>,
                         cudaFuncAttributeMaxDynamicSharedMemorySize, smem1);

    transpose_kernel<<<(S_LEN * D_IN * B_SZ + 255) / 256, 256>>>(x);
    lstm_kernel<D_IN, 64><<<NCTA, 256, smem0>>>(W_ih0, W_hh0, b_ih0, b_hh0);
    lstm_kernel<H_SZ, 128><<<NCTA, 256, smem1>>>(W_ih1, W_hh1, b_ih1, b_hh1);
    energy_kernel<<<S_LEN, 256>>>(W_a, b_a, v_a, b_v);
    entmax_kernel<<<B_SZ, 512>>>(out);
    ctx1_kernel<<<64, 256>>>();
    ctx2_kernel<<<(H_SZ * B_SZ + 255) / 256, 256>>>();
    fc_kernel<<<1, 128>>>(fc_W, fc_b, out);
}